// round 2
// baseline (speedup 1.0000x reference)
#include <cuda_runtime.h>
#include <math.h>

// Problem constants (from setup_inputs: b=2, n=4096, q=16384)
#define B_    2
#define NPTS  4096
#define NQ    16384
#define NTOT  (B_*NQ)      // 32768 query points total
#define NPTOT (B_*NPTS)    // 8192 original points total
#define C1 64
#define C2 128
#define C3 256
#define AGGC 707           // 3 + 64 + 128 + 256 + 256
#define GMAX_PARTS 32      // partial blocks per batch for global max

// ------------------------- device scratch (no allocs) -------------------------
__device__ float g_F1[(size_t)NPTOT*C1];     // [pt][64]  per-point features (transposed)
__device__ float g_F2[(size_t)NPTOT*C2];     // [pt][128]
__device__ float g_F3[(size_t)NPTOT*C3];     // [pt][256]
__device__ float g_Gp[B_*GMAX_PARTS*C3];     // partial maxes
__device__ float g_G [B_*C3];                // global max feats
__device__ int   g_idx[NTOT*3];
__device__ float g_wt [NTOT*3];
__device__ float g_AGG[(size_t)NTOT*AGGC];   // [query][707]
__device__ float g_H1[(size_t)NTOT*256];
__device__ float g_H2[(size_t)NTOT*128];
__device__ float g_H3[(size_t)NTOT*64];

// ------------------------- layer 1 (3 -> 64) -------------------------
__global__ void f1_kernel(const float* __restrict__ P,
                          const float* __restrict__ w1,
                          const float* __restrict__ b1)
{
    int t = blockIdx.x*blockDim.x + threadIdx.x;
    if (t >= NPTOT*C1) return;
    int c = t & 63;
    int j = t >> 6;              // global point index
    int b = j / NPTS, i = j - b*NPTS;
    const float* pb = P + (size_t)b*3*NPTS + i;
    float x0 = pb[0], x1 = pb[NPTS], x2 = pb[2*NPTS];
    float v = b1[c] + w1[c*3+0]*x0 + w1[c*3+1]*x1 + w1[c*3+2]*x2;
    g_F1[t] = fmaxf(v, 0.f);
}

// ------------------------- generic TN GEMM: C[N][M] = act(W[M][K] * X[N][K]^T + bias) -------------------------
#define GMT 128
#define GNT 64
#define GKC 32

template<bool RELU>
__global__ void __launch_bounds__(256)
gemm_tn(const float* __restrict__ W, const float* __restrict__ X,
        const float* __restrict__ bias, float* __restrict__ C,
        int M, int N, int K)
{
    __shared__ float sW[GKC][GMT+1];
    __shared__ float sX[GKC][GNT+1];
    int tid  = threadIdx.x;
    int warp = tid >> 5, lane = tid & 31;
    int m0 = blockIdx.y * GMT;
    int n0 = blockIdx.x * GNT;
    int tn = tid & 15;     // n micro group (x4)
    int tm = tid >> 4;     // m micro group (x8)

    float acc[8][4];
    #pragma unroll
    for (int i = 0; i < 8; i++)
        #pragma unroll
        for (int j = 0; j < 4; j++) acc[i][j] = 0.f;

    for (int k0 = 0; k0 < K; k0 += GKC) {
        int kk = k0 + lane;
        bool kv = kk < K;
        // W tile: 128 rows x 32 k, each warp loads 16 rows (coalesced per row)
        #pragma unroll
        for (int r = 0; r < 16; r++) {
            int m = m0 + warp*16 + r;
            float v = (kv && m < M) ? W[(size_t)m*K + kk] : 0.f;
            sW[lane][warp*16 + r] = v;
        }
        // X tile: 64 rows x 32 k, each warp loads 8 rows
        #pragma unroll
        for (int r = 0; r < 8; r++) {
            int n = n0 + warp*8 + r;
            float v = kv ? X[(size_t)n*K + kk] : 0.f;
            sX[lane][warp*8 + r] = v;
        }
        __syncthreads();
        #pragma unroll 8
        for (int k2 = 0; k2 < GKC; k2++) {
            float a[8], bb[4];
            #pragma unroll
            for (int i = 0; i < 8; i++) a[i] = sW[k2][tm*8 + i];
            #pragma unroll
            for (int j = 0; j < 4; j++) bb[j] = sX[k2][tn*4 + j];
            #pragma unroll
            for (int i = 0; i < 8; i++)
                #pragma unroll
                for (int j = 0; j < 4; j++)
                    acc[i][j] = fmaf(a[i], bb[j], acc[i][j]);
        }
        __syncthreads();
    }

    #pragma unroll
    for (int j = 0; j < 4; j++) {
        int n = n0 + tn*4 + j;
        float* crow = C + (size_t)n*M;
        #pragma unroll
        for (int i = 0; i < 8; i++) {
            int m = m0 + tm*8 + i;
            if (m < M) {
                float v = acc[i][j] + bias[m];
                crow[m] = RELU ? fmaxf(v, 0.f) : v;
            }
        }
    }
}

// ------------------------- global max over points per (b, channel), 2-stage -------------------------
__global__ void gmax_part_kernel()
{
    // grid: (B_, GMAX_PARTS); block: 256 threads = 256 channels
    int b = blockIdx.x, part = blockIdx.y;
    int c = threadIdx.x;
    int i0 = part * (NPTS/GMAX_PARTS);
    const float* base = g_F3 + (size_t)(b*NPTS + i0)*C3 + c;
    float m = 0.f;   // F3 is post-ReLU, >= 0
    #pragma unroll 4
    for (int i = 0; i < NPTS/GMAX_PARTS; i++) m = fmaxf(m, base[(size_t)i*C3]);
    g_Gp[(b*GMAX_PARTS + part)*C3 + c] = m;
}

__global__ void gmax_final_kernel()
{
    int b = blockIdx.x;
    int c = threadIdx.x;
    float m = 0.f;
    #pragma unroll
    for (int p = 0; p < GMAX_PARTS; p++)
        m = fmaxf(m, g_Gp[(b*GMAX_PARTS + p)*C3 + c]);
    g_G[b*C3 + c] = m;
}

// ------------------------- KNN top-3 + inverse-distance weights -------------------------
extern __shared__ float4 s_pts[];   // [NPTS] : (x, y, z, 0.5*|p|^2)  = 64 KB

__global__ void knn_kernel(const float* __restrict__ P, const float* __restrict__ Q)
{
    int b = blockIdx.y;
    const float* Pb = P + (size_t)b*3*NPTS;
    for (int i = threadIdx.x; i < NPTS; i += blockDim.x) {
        float x = Pb[i], y = Pb[NPTS+i], z = Pb[2*NPTS+i];
        s_pts[i] = make_float4(x, y, z, 0.5f*(x*x + y*y + z*z));
    }
    __syncthreads();

    int qi = blockIdx.x*blockDim.x + threadIdx.x;
    const float* Qb = Q + (size_t)b*3*NQ;
    float qx = Qb[qi], qy = Qb[NQ+qi], qz = Qb[2*NQ+qi];

    // maximize s = q.p - 0.5|p|^2  <=>  minimize squared distance.
    // Branchless predicated top-3 (strict > keeps the earliest index, matching
    // jax.lax.top_k tie order).
    float s0 = -1e30f, s1 = -1e30f, s2 = -1e30f;
    int   i0 = 0, i1 = 0, i2 = 0;
    #pragma unroll 4
    for (int i = 0; i < NPTS; i++) {
        float4 p = s_pts[i];   // broadcast LDS.128
        float s = fmaf(qx, p.x, fmaf(qy, p.y, fmaf(qz, p.z, -p.w)));
        bool gt0 = s > s0, gt1 = s > s1, gt2 = s > s2;
        s2 = gt1 ? s1 : (gt2 ? s : s2);
        i2 = gt1 ? i1 : (gt2 ? i : i2);
        s1 = gt0 ? s0 : (gt1 ? s : s1);
        i1 = gt0 ? i0 : (gt1 ? i : i1);
        s0 = gt0 ? s  : s0;
        i0 = gt0 ? i  : i0;
    }

    int j = b*NQ + qi;
    int idx[3] = {i0, i1, i2};
    float r[3];
    #pragma unroll
    for (int k = 0; k < 3; k++) {
        float4 p = s_pts[idx[k]];
        float dx = qx - p.x, dy = qy - p.y, dz = qz - p.z;
        float d = sqrtf(dx*dx + dy*dy + dz*dz);
        r[k] = 1.f/(d + 1e-8f);
    }
    float rs = r[0] + r[1] + r[2];
    #pragma unroll
    for (int k = 0; k < 3; k++) {
        g_idx[j*3 + k] = idx[k];
        g_wt [j*3 + k] = r[k]/rs;
    }
}

// ------------------------- build AGG[j][707] : [query(3) | f1 | f2 | f3 | global] -------------------------
__global__ void agg_kernel(const float* __restrict__ Q)
{
    int warp = threadIdx.x >> 5, lane = threadIdx.x & 31;
    int j = blockIdx.x*8 + warp;          // one warp per query
    if (j >= NTOT) return;
    int b = j / NQ, qi = j - b*NQ;

    int   i0 = g_idx[j*3+0], i1 = g_idx[j*3+1], i2 = g_idx[j*3+2];
    float w0 = g_wt [j*3+0], w1 = g_wt [j*3+1], w2 = g_wt [j*3+2];
    float* a = g_AGG + (size_t)j*AGGC;

    if (lane < 3) a[lane] = Q[(size_t)b*3*NQ + lane*NQ + qi];

    {
        const float* fa = g_F1 + (size_t)(b*NPTS + i0)*C1;
        const float* fb = g_F1 + (size_t)(b*NPTS + i1)*C1;
        const float* fc = g_F1 + (size_t)(b*NPTS + i2)*C1;
        #pragma unroll
        for (int c = lane; c < C1; c += 32)
            a[3 + c] = w0*fa[c] + w1*fb[c] + w2*fc[c];
    }
    {
        const float* fa = g_F2 + (size_t)(b*NPTS + i0)*C2;
        const float* fb = g_F2 + (size_t)(b*NPTS + i1)*C2;
        const float* fc = g_F2 + (size_t)(b*NPTS + i2)*C2;
        #pragma unroll
        for (int c = lane; c < C2; c += 32)
            a[67 + c] = w0*fa[c] + w1*fb[c] + w2*fc[c];
    }
    {
        const float* fa = g_F3 + (size_t)(b*NPTS + i0)*C3;
        const float* fb = g_F3 + (size_t)(b*NPTS + i1)*C3;
        const float* fc = g_F3 + (size_t)(b*NPTS + i2)*C3;
        #pragma unroll
        for (int c = lane; c < C3; c += 32)
            a[195 + c] = w0*fa[c] + w1*fb[c] + w2*fc[c];
    }
    #pragma unroll
    for (int c = lane; c < C3; c += 32)
        a[451 + c] = g_G[b*C3 + c];
}

// ------------------------- final layer: 64 -> 1 -------------------------
__global__ void final_kernel(const float* __restrict__ r4,
                             const float* __restrict__ rb4,
                             float* __restrict__ out)
{
    __shared__ float w[64];
    if (threadIdx.x < 64) w[threadIdx.x] = r4[threadIdx.x];
    __syncthreads();
    int j = blockIdx.x*blockDim.x + threadIdx.x;   // grid exact: NTOT threads
    const float4* h4 = (const float4*)(g_H3 + (size_t)j*64);
    float s = rb4[0];
    #pragma unroll
    for (int c = 0; c < 16; c++) {
        float4 v = h4[c];
        s += w[4*c+0]*v.x + w[4*c+1]*v.y + w[4*c+2]*v.z + w[4*c+3]*v.w;
    }
    out[j] = s;
}

// ------------------------- launch -------------------------
extern "C" void kernel_launch(void* const* d_in, const int* in_sizes, int n_in,
                              void* d_out, int out_size)
{
    const float* P   = (const float*)d_in[0];   // original_pts (b,3,n)
    const float* Q   = (const float*)d_in[1];   // query_pts    (b,3,q)
    const float* w1  = (const float*)d_in[2];
    const float* b1  = (const float*)d_in[3];
    const float* w2  = (const float*)d_in[4];
    const float* b2  = (const float*)d_in[5];
    const float* w3  = (const float*)d_in[6];
    const float* b3  = (const float*)d_in[7];
    const float* r1  = (const float*)d_in[8];
    const float* rb1 = (const float*)d_in[9];
    const float* r2  = (const float*)d_in[10];
    const float* rb2 = (const float*)d_in[11];
    const float* r3  = (const float*)d_in[12];
    const float* rb3 = (const float*)d_in[13];
    const float* r4  = (const float*)d_in[14];
    const float* rb4 = (const float*)d_in[15];
    float* out = (float*)d_out;

    void* p;
    float *F1, *F2, *F3, *AGG, *H1, *H2, *H3;
    cudaGetSymbolAddress(&p, g_F1);  F1  = (float*)p;
    cudaGetSymbolAddress(&p, g_F2);  F2  = (float*)p;
    cudaGetSymbolAddress(&p, g_F3);  F3  = (float*)p;
    cudaGetSymbolAddress(&p, g_AGG); AGG = (float*)p;
    cudaGetSymbolAddress(&p, g_H1);  H1  = (float*)p;
    cudaGetSymbolAddress(&p, g_H2);  H2  = (float*)p;
    cudaGetSymbolAddress(&p, g_H3);  H3  = (float*)p;

    cudaFuncSetAttribute(knn_kernel,
                         cudaFuncAttributeMaxDynamicSharedMemorySize,
                         NPTS * (int)sizeof(float4));

    // Feature extractor
    f1_kernel<<<(NPTOT*C1 + 255)/256, 256>>>(P, w1, b1);
    gemm_tn<true><<<dim3(NPTOT/GNT, 1), 256>>>(w2, F1, b2, F2, C2, NPTOT, C1);
    gemm_tn<true><<<dim3(NPTOT/GNT, 2), 256>>>(w3, F2, b3, F3, C3, NPTOT, C2);
    gmax_part_kernel<<<dim3(B_, GMAX_PARTS), 256>>>();
    gmax_final_kernel<<<B_, 256>>>();

    // KNN + interpolation + aggregation
    knn_kernel<<<dim3(NQ/256, B_), 256, NPTS*sizeof(float4)>>>(P, Q);
    agg_kernel<<<NTOT/8, 256>>>(Q);

    // Regressor
    gemm_tn<true><<<dim3(NTOT/GNT, 2), 256>>>(r1, AGG, rb1, H1, 256, NTOT, AGGC);
    gemm_tn<true><<<dim3(NTOT/GNT, 1), 256>>>(r2, H1, rb2, H2, 128, NTOT, 256);
    gemm_tn<true><<<dim3(NTOT/GNT, 1), 256>>>(r3, H2, rb3, H3, 64, NTOT, 128);
    final_kernel<<<NTOT/256, 256>>>(r4, rb4, out);
}

// round 15
// speedup vs baseline: 1.6098x; 1.6098x over previous
#include <cuda_runtime.h>
#include <cuda_bf16.h>
#include <mma.h>
#include <math.h>
#include <stdint.h>

using namespace nvcuda;

// Problem constants (setup_inputs: b=2, n=4096, q=16384)
#define B_    2
#define NPTS  4096
#define NQ    16384
#define NTOT  (B_*NQ)      // 32768 query points
#define NPTOT (B_*NPTS)    // 8192 original points
#define C1 64
#define C2 128
#define C3 256
#define AGGC 707
#define KP1 768            // AGG padded K (multiple of 32)
#define GMAX_PARTS 128

// ------------------------- device scratch (no allocs) -------------------------
__device__ __align__(256) float g_F1[(size_t)NPTOT*C1];
__device__ __align__(256) float g_F2[(size_t)NPTOT*C2];
__device__ __align__(256) float g_F3[(size_t)NPTOT*C3];
__device__ __align__(256) float g_Gp[B_*GMAX_PARTS*C3];
__device__ __align__(256) float g_G [B_*C3];
__device__ int   g_idx[NTOT*3];
__device__ float g_wt [NTOT*3];
__device__ __align__(256) __nv_bfloat16 g_AGGh[(size_t)NTOT*KP1];
__device__ __align__(256) __nv_bfloat16 g_AGGl[(size_t)NTOT*KP1];
__device__ __align__(256) __nv_bfloat16 g_H1h[(size_t)NTOT*256];
__device__ __align__(256) __nv_bfloat16 g_H1l[(size_t)NTOT*256];
__device__ __align__(256) __nv_bfloat16 g_H2h[(size_t)NTOT*128];
__device__ __align__(256) __nv_bfloat16 g_H2l[(size_t)NTOT*128];
__device__ __align__(256) float g_H3[(size_t)NTOT*64];
__device__ __align__(256) __nv_bfloat16 g_W1h[256*KP1];
__device__ __align__(256) __nv_bfloat16 g_W1l[256*KP1];
__device__ __align__(256) __nv_bfloat16 g_W2h[128*256];
__device__ __align__(256) __nv_bfloat16 g_W2l[128*256];
__device__ __align__(256) __nv_bfloat16 g_W3h[64*128];
__device__ __align__(256) __nv_bfloat16 g_W3l[64*128];

__device__ __forceinline__ void bf16_split(float v, __nv_bfloat16& h, __nv_bfloat16& l) {
    h = __float2bfloat16(v);
    l = __float2bfloat16(v - __bfloat162float(h));
}

// ------------------------- layer 1 (3 -> 64), fp32 -------------------------
__global__ void f1_kernel(const float* __restrict__ P,
                          const float* __restrict__ w1,
                          const float* __restrict__ b1)
{
    int t = blockIdx.x*blockDim.x + threadIdx.x;
    if (t >= NPTOT*C1) return;
    int c = t & 63;
    int j = t >> 6;
    int b = j / NPTS, i = j - b*NPTS;
    const float* pb = P + (size_t)b*3*NPTS + i;
    float x0 = pb[0], x1 = pb[NPTS], x2 = pb[2*NPTS];
    float v = b1[c] + w1[c*3+0]*x0 + w1[c*3+1]*x1 + w1[c*3+2]*x2;
    g_F1[t] = fmaxf(v, 0.f);
}

// ------------------------- fp32 SIMT GEMM (feature extractor only) -------------------------
#define GMT 128
#define GNT 64
#define GKC 32
template<bool RELU>
__global__ void __launch_bounds__(256)
gemm_tn(const float* __restrict__ W, const float* __restrict__ X,
        const float* __restrict__ bias, float* __restrict__ C,
        int M, int N, int K)
{
    __shared__ float sW[GKC][GMT+1];
    __shared__ float sX[GKC][GNT+1];
    int tid  = threadIdx.x;
    int warp = tid >> 5, lane = tid & 31;
    int m0 = blockIdx.y * GMT;
    int n0 = blockIdx.x * GNT;
    int tn = tid & 15;
    int tm = tid >> 4;

    float acc[8][4];
    #pragma unroll
    for (int i = 0; i < 8; i++)
        #pragma unroll
        for (int j = 0; j < 4; j++) acc[i][j] = 0.f;

    for (int k0 = 0; k0 < K; k0 += GKC) {
        int kk = k0 + lane;
        bool kv = kk < K;
        #pragma unroll
        for (int r = 0; r < 16; r++) {
            int m = m0 + warp*16 + r;
            sW[lane][warp*16 + r] = (kv && m < M) ? W[(size_t)m*K + kk] : 0.f;
        }
        #pragma unroll
        for (int r = 0; r < 8; r++) {
            int n = n0 + warp*8 + r;
            sX[lane][warp*8 + r] = kv ? X[(size_t)n*K + kk] : 0.f;
        }
        __syncthreads();
        #pragma unroll 8
        for (int k2 = 0; k2 < GKC; k2++) {
            float a[8], bb[4];
            #pragma unroll
            for (int i = 0; i < 8; i++) a[i] = sW[k2][tm*8 + i];
            #pragma unroll
            for (int j = 0; j < 4; j++) bb[j] = sX[k2][tn*4 + j];
            #pragma unroll
            for (int i = 0; i < 8; i++)
                #pragma unroll
                for (int j = 0; j < 4; j++)
                    acc[i][j] = fmaf(a[i], bb[j], acc[i][j]);
        }
        __syncthreads();
    }
    #pragma unroll
    for (int j = 0; j < 4; j++) {
        int n = n0 + tn*4 + j;
        float* crow = C + (size_t)n*M;
        #pragma unroll
        for (int i = 0; i < 8; i++) {
            int m = m0 + tm*8 + i;
            if (m < M) {
                float v = acc[i][j] + bias[m];
                crow[m] = RELU ? fmaxf(v, 0.f) : v;
            }
        }
    }
}

// ------------------------- global max, 2-stage -------------------------
__global__ void gmax_part_kernel()
{
    int b = blockIdx.x, part = blockIdx.y;
    int c = threadIdx.x;
    int i0 = part * (NPTS/GMAX_PARTS);
    const float* base = g_F3 + (size_t)(b*NPTS + i0)*C3 + c;
    float m = 0.f;
    #pragma unroll 4
    for (int i = 0; i < NPTS/GMAX_PARTS; i++) m = fmaxf(m, base[(size_t)i*C3]);
    g_Gp[(b*GMAX_PARTS + part)*C3 + c] = m;
}
__global__ void gmax_final_kernel()
{
    int b = blockIdx.x, c = threadIdx.x;
    float m = 0.f;
    #pragma unroll 8
    for (int p = 0; p < GMAX_PARTS; p++)
        m = fmaxf(m, g_Gp[(b*GMAX_PARTS + p)*C3 + c]);
    g_G[b*C3 + c] = m;
}

// ------------------------- KNN top-3 + weights -------------------------
__global__ void knn_kernel(const float* __restrict__ P, const float* __restrict__ Q)
{
    extern __shared__ float4 s_pts[];   // [NPTS] : (x, y, z, 0.5*|p|^2) = 64 KB
    int b = blockIdx.y;
    const float* Pb = P + (size_t)b*3*NPTS;
    for (int i = threadIdx.x; i < NPTS; i += blockDim.x) {
        float x = Pb[i], y = Pb[NPTS+i], z = Pb[2*NPTS+i];
        s_pts[i] = make_float4(x, y, z, 0.5f*(x*x + y*y + z*z));
    }
    __syncthreads();

    int qi = blockIdx.x*blockDim.x + threadIdx.x;
    const float* Qb = Q + (size_t)b*3*NQ;
    float qx = Qb[qi], qy = Qb[NQ+qi], qz = Qb[2*NQ+qi];

    float s0 = -1e30f, s1 = -1e30f, s2 = -1e30f;
    int   i0 = 0, i1 = 0, i2 = 0;
    #pragma unroll 4
    for (int i = 0; i < NPTS; i++) {
        float4 p = s_pts[i];
        float s = fmaf(qx, p.x, fmaf(qy, p.y, fmaf(qz, p.z, -p.w)));
        bool gt0 = s > s0, gt1 = s > s1, gt2 = s > s2;
        s2 = gt1 ? s1 : (gt2 ? s : s2);
        i2 = gt1 ? i1 : (gt2 ? i : i2);
        s1 = gt0 ? s0 : (gt1 ? s : s1);
        i1 = gt0 ? i0 : (gt1 ? i : i1);
        s0 = gt0 ? s  : s0;
        i0 = gt0 ? i  : i0;
    }

    int j = b*NQ + qi;
    int idx[3] = {i0, i1, i2};
    float r[3];
    #pragma unroll
    for (int k = 0; k < 3; k++) {
        float4 p = s_pts[idx[k]];
        float dx = qx - p.x, dy = qy - p.y, dz = qz - p.z;
        float d = sqrtf(dx*dx + dy*dy + dz*dz);
        r[k] = 1.f/(d + 1e-8f);
    }
    float rs = r[0] + r[1] + r[2];
    #pragma unroll
    for (int k = 0; k < 3; k++) {
        g_idx[j*3 + k] = idx[k];
        g_wt [j*3 + k] = r[k]/rs;
    }
}

// ------------------------- AGG build -> split bf16 [q][768] -------------------------
__device__ __forceinline__ void split_store(size_t off, float v) {
    __nv_bfloat16 h, l; bf16_split(v, h, l);
    g_AGGh[off] = h; g_AGGl[off] = l;
}

__global__ void agg_kernel(const float* __restrict__ Q)
{
    int warp = threadIdx.x >> 5, lane = threadIdx.x & 31;
    int j = blockIdx.x*8 + warp;
    if (j >= NTOT) return;
    int b = j / NQ, qi = j - b*NQ;

    int   i0 = g_idx[j*3+0], i1 = g_idx[j*3+1], i2 = g_idx[j*3+2];
    float w0 = g_wt [j*3+0], w1 = g_wt [j*3+1], w2 = g_wt [j*3+2];
    size_t base = (size_t)j*KP1;

    if (lane < 3) split_store(base + lane, Q[(size_t)b*3*NQ + lane*NQ + qi]);

    {
        const float* fa = g_F1 + (size_t)(b*NPTS + i0)*C1;
        const float* fb = g_F1 + (size_t)(b*NPTS + i1)*C1;
        const float* fc = g_F1 + (size_t)(b*NPTS + i2)*C1;
        #pragma unroll
        for (int c = lane; c < C1; c += 32)
            split_store(base + 3 + c, w0*fa[c] + w1*fb[c] + w2*fc[c]);
    }
    {
        const float* fa = g_F2 + (size_t)(b*NPTS + i0)*C2;
        const float* fb = g_F2 + (size_t)(b*NPTS + i1)*C2;
        const float* fc = g_F2 + (size_t)(b*NPTS + i2)*C2;
        #pragma unroll
        for (int c = lane; c < C2; c += 32)
            split_store(base + 67 + c, w0*fa[c] + w1*fb[c] + w2*fc[c]);
    }
    {
        const float* fa = g_F3 + (size_t)(b*NPTS + i0)*C3;
        const float* fb = g_F3 + (size_t)(b*NPTS + i1)*C3;
        const float* fc = g_F3 + (size_t)(b*NPTS + i2)*C3;
        #pragma unroll
        for (int c = lane; c < C3; c += 32)
            split_store(base + 195 + c, w0*fa[c] + w1*fb[c] + w2*fc[c]);
    }
    #pragma unroll
    for (int c = lane; c < C3; c += 32)
        split_store(base + 451 + c, g_G[b*C3 + c]);
    // zero padding [707, 768)
    for (int c = AGGC + lane; c < KP1; c += 32) {
        g_AGGh[base + c] = __float2bfloat16(0.f);
        g_AGGl[base + c] = __float2bfloat16(0.f);
    }
}

// ------------------------- weight split (fp32 -> bf16 hi/lo, K-padded) -------------------------
__global__ void wsplit_kernel(const float* __restrict__ W,
                              __nv_bfloat16* __restrict__ Wh,
                              __nv_bfloat16* __restrict__ Wl,
                              int NOUT, int K, int KPp)
{
    int t = blockIdx.x*blockDim.x + threadIdx.x;
    if (t >= NOUT*KPp) return;
    int m = t / KPp, k = t - m*KPp;
    float v = (k < K) ? W[(size_t)m*K + k] : 0.f;
    __nv_bfloat16 h, l; bf16_split(v, h, l);
    Wh[t] = h; Wl[t] = l;
}

// ------------------------- WMMA split-bf16 GEMM (portable HMMA, no 'a'-features) ------------
// C[q][NOUT] = relu(sum_k X[q][k]*W[n][k] + bias), X = Xh+Xl, W = Wh+Wl,
// computed as Xh*Wh + Xl*Wh + Xh*Wl with fp32 accumulate.
// CTA tile: 128 queries x 64 outputs; grid (NTOT/128, NOUT/64).
// 8 warps in 4(M) x 2(N); warp tile 32x32 = 2x2 m16n16k16 fragments.
#define XS 40   // smem tile stride in bf16 (32 data + 8 pad, mult of 8)
#define CS 72   // C smem stride in floats (64 + 8 pad, mult of 4)

template<int NOUT, int KPAD, bool SPLIT_OUT>
__global__ void __launch_bounds__(256)
wm_gemm(const __nv_bfloat16* __restrict__ Ah, const __nv_bfloat16* __restrict__ Al,
        const __nv_bfloat16* __restrict__ Wh, const __nv_bfloat16* __restrict__ Wl,
        const float* __restrict__ bias,
        __nv_bfloat16* __restrict__ Oh, __nv_bfloat16* __restrict__ Ol,
        float* __restrict__ Ofp)
{
    // union: tiles (30,720 B) overlaid by C (128*72*4 = 36,864 B); bias after.
    __shared__ __align__(16) char smr[128*CS*4 + 256];
    __nv_bfloat16* sXh = (__nv_bfloat16*)(smr);
    __nv_bfloat16* sXl = (__nv_bfloat16*)(smr + 10240);
    __nv_bfloat16* sWh = (__nv_bfloat16*)(smr + 20480);
    __nv_bfloat16* sWl = (__nv_bfloat16*)(smr + 25600);
    float* sC = (float*)smr;
    float* sB = (float*)(smr + 128*CS*4);

    int tid = threadIdx.x, wid = tid >> 5;
    size_t q0 = (size_t)blockIdx.x * 128;
    int n0 = blockIdx.y * 64;
    int wm = wid & 3, wn = wid >> 2;

    if (tid < 64) sB[tid] = bias[n0 + tid];

    wmma::fragment<wmma::accumulator, 16, 16, 16, float> c[2][2];
    #pragma unroll
    for (int i = 0; i < 2; i++)
        #pragma unroll
        for (int j = 0; j < 2; j++) wmma::fill_fragment(c[i][j], 0.f);

    for (int k0 = 0; k0 < KPAD; k0 += 32) {
        __syncthreads();
        // X tiles: 128 rows x 32 bf16; 4 16B-chunks/row = 512 chunks -> 2/thread
        #pragma unroll
        for (int it = 0; it < 2; it++) {
            int ci = it*256 + tid;
            int r = ci >> 2, cc = ci & 3;
            *(uint4*)(sXh + r*XS + cc*8) = *(const uint4*)(Ah + (q0 + r)*KPAD + k0 + cc*8);
            *(uint4*)(sXl + r*XS + cc*8) = *(const uint4*)(Al + (q0 + r)*KPAD + k0 + cc*8);
        }
        // W tiles: 64 rows x 32 bf16; 256 chunks -> 1/thread
        {
            int r = tid >> 2, cc = tid & 3;
            *(uint4*)(sWh + r*XS + cc*8) = *(const uint4*)(Wh + (size_t)(n0 + r)*KPAD + k0 + cc*8);
            *(uint4*)(sWl + r*XS + cc*8) = *(const uint4*)(Wl + (size_t)(n0 + r)*KPAD + k0 + cc*8);
        }
        __syncthreads();
        #pragma unroll
        for (int kk = 0; kk < 32; kk += 16) {
            wmma::fragment<wmma::matrix_a, 16, 16, 16, __nv_bfloat16, wmma::row_major> ah[2], al[2];
            wmma::fragment<wmma::matrix_b, 16, 16, 16, __nv_bfloat16, wmma::col_major> bh[2], bl[2];
            #pragma unroll
            for (int mt = 0; mt < 2; mt++) {
                wmma::load_matrix_sync(ah[mt], sXh + (wm*32 + mt*16)*XS + kk, XS);
                wmma::load_matrix_sync(al[mt], sXl + (wm*32 + mt*16)*XS + kk, XS);
            }
            #pragma unroll
            for (int nt = 0; nt < 2; nt++) {
                wmma::load_matrix_sync(bh[nt], sWh + (wn*32 + nt*16)*XS + kk, XS);
                wmma::load_matrix_sync(bl[nt], sWl + (wn*32 + nt*16)*XS + kk, XS);
            }
            #pragma unroll
            for (int mt = 0; mt < 2; mt++)
                #pragma unroll
                for (int nt = 0; nt < 2; nt++) {
                    wmma::mma_sync(c[mt][nt], ah[mt], bh[nt], c[mt][nt]);
                    wmma::mma_sync(c[mt][nt], al[mt], bh[nt], c[mt][nt]);
                    wmma::mma_sync(c[mt][nt], ah[mt], bl[nt], c[mt][nt]);
                }
        }
    }
    __syncthreads();
    #pragma unroll
    for (int mt = 0; mt < 2; mt++)
        #pragma unroll
        for (int nt = 0; nt < 2; nt++)
            wmma::store_matrix_sync(sC + (wm*32 + mt*16)*CS + wn*32 + nt*16,
                                    c[mt][nt], CS, wmma::mem_row_major);
    __syncthreads();

    // epilogue: 128 rows x 64 cols = 2048 float4s -> 8/thread
    #pragma unroll
    for (int it = 0; it < 8; it++) {
        int ci = it*256 + tid;
        int r = ci >> 4, c4 = (ci & 15)*4;
        size_t q = q0 + r;
        float4 v = *(float4*)(sC + r*CS + c4);
        v.x = fmaxf(v.x + sB[c4+0], 0.f);
        v.y = fmaxf(v.y + sB[c4+1], 0.f);
        v.z = fmaxf(v.z + sB[c4+2], 0.f);
        v.w = fmaxf(v.w + sB[c4+3], 0.f);
        if (SPLIT_OUT) {
            __nv_bfloat16 h0,l0,h1,l1,h2,l2,h3,l3;
            bf16_split(v.x, h0, l0); bf16_split(v.y, h1, l1);
            bf16_split(v.z, h2, l2); bf16_split(v.w, h3, l3);
            uint2 ph, pl;
            ph.x = (uint32_t)__bfloat16_as_ushort(h0) | ((uint32_t)__bfloat16_as_ushort(h1) << 16);
            ph.y = (uint32_t)__bfloat16_as_ushort(h2) | ((uint32_t)__bfloat16_as_ushort(h3) << 16);
            pl.x = (uint32_t)__bfloat16_as_ushort(l0) | ((uint32_t)__bfloat16_as_ushort(l1) << 16);
            pl.y = (uint32_t)__bfloat16_as_ushort(l2) | ((uint32_t)__bfloat16_as_ushort(l3) << 16);
            *(uint2*)(Oh + q*NOUT + n0 + c4) = ph;
            *(uint2*)(Ol + q*NOUT + n0 + c4) = pl;
        } else {
            *(float4*)(Ofp + q*NOUT + n0 + c4) = v;
        }
    }
}

// ------------------------- final layer: 64 -> 1 -------------------------
__global__ void final_kernel(const float* __restrict__ r4,
                             const float* __restrict__ rb4,
                             float* __restrict__ out)
{
    __shared__ float w[64];
    if (threadIdx.x < 64) w[threadIdx.x] = r4[threadIdx.x];
    __syncthreads();
    int j = blockIdx.x*blockDim.x + threadIdx.x;
    const float4* h4 = (const float4*)(g_H3 + (size_t)j*64);
    float s = rb4[0];
    #pragma unroll
    for (int c = 0; c < 16; c++) {
        float4 v = h4[c];
        s += w[4*c+0]*v.x + w[4*c+1]*v.y + w[4*c+2]*v.z + w[4*c+3]*v.w;
    }
    out[j] = s;
}

// ------------------------- launch -------------------------
extern "C" void kernel_launch(void* const* d_in, const int* in_sizes, int n_in,
                              void* d_out, int out_size)
{
    const float* P   = (const float*)d_in[0];
    const float* Q   = (const float*)d_in[1];
    const float* w1  = (const float*)d_in[2];
    const float* b1  = (const float*)d_in[3];
    const float* w2  = (const float*)d_in[4];
    const float* b2  = (const float*)d_in[5];
    const float* w3  = (const float*)d_in[6];
    const float* b3  = (const float*)d_in[7];
    const float* r1  = (const float*)d_in[8];
    const float* rb1 = (const float*)d_in[9];
    const float* r2  = (const float*)d_in[10];
    const float* rb2 = (const float*)d_in[11];
    const float* r3  = (const float*)d_in[12];
    const float* rb3 = (const float*)d_in[13];
    const float* r4  = (const float*)d_in[14];
    const float* rb4 = (const float*)d_in[15];
    float* out = (float*)d_out;

    void* p;
    float *F1, *F2, *F3, *H3;
    __nv_bfloat16 *AGGh, *AGGl, *H1h, *H1l, *H2h, *H2l;
    __nv_bfloat16 *W1h, *W1l, *W2h, *W2l, *W3h, *W3l;
    cudaGetSymbolAddress(&p, g_F1);   F1   = (float*)p;
    cudaGetSymbolAddress(&p, g_F2);   F2   = (float*)p;
    cudaGetSymbolAddress(&p, g_F3);   F3   = (float*)p;
    cudaGetSymbolAddress(&p, g_AGGh); AGGh = (__nv_bfloat16*)p;
    cudaGetSymbolAddress(&p, g_AGGl); AGGl = (__nv_bfloat16*)p;
    cudaGetSymbolAddress(&p, g_H1h);  H1h  = (__nv_bfloat16*)p;
    cudaGetSymbolAddress(&p, g_H1l);  H1l  = (__nv_bfloat16*)p;
    cudaGetSymbolAddress(&p, g_H2h);  H2h  = (__nv_bfloat16*)p;
    cudaGetSymbolAddress(&p, g_H2l);  H2l  = (__nv_bfloat16*)p;
    cudaGetSymbolAddress(&p, g_H3);   H3   = (float*)p;
    cudaGetSymbolAddress(&p, g_W1h);  W1h  = (__nv_bfloat16*)p;
    cudaGetSymbolAddress(&p, g_W1l);  W1l  = (__nv_bfloat16*)p;
    cudaGetSymbolAddress(&p, g_W2h);  W2h  = (__nv_bfloat16*)p;
    cudaGetSymbolAddress(&p, g_W2l);  W2l  = (__nv_bfloat16*)p;
    cudaGetSymbolAddress(&p, g_W3h);  W3h  = (__nv_bfloat16*)p;
    cudaGetSymbolAddress(&p, g_W3l);  W3l  = (__nv_bfloat16*)p;

    cudaFuncSetAttribute(knn_kernel,
                         cudaFuncAttributeMaxDynamicSharedMemorySize,
                         NPTS * (int)sizeof(float4));

    // Feature extractor (fp32)
    f1_kernel<<<(NPTOT*C1 + 255)/256, 256>>>(P, w1, b1);
    gemm_tn<true><<<dim3(NPTOT/GNT, 1), 256>>>(w2, F1, b2, F2, C2, NPTOT, C1);
    gemm_tn<true><<<dim3(NPTOT/GNT, 2), 256>>>(w3, F2, b3, F3, C3, NPTOT, C2);
    gmax_part_kernel<<<dim3(B_, GMAX_PARTS), 256>>>();
    gmax_final_kernel<<<B_, 256>>>();

    // Weight splits (small)
    wsplit_kernel<<<(256*KP1 + 255)/256, 256>>>(r1, W1h, W1l, 256, AGGC, KP1);
    wsplit_kernel<<<(128*256 + 255)/256, 256>>>(r2, W2h, W2l, 128, 256, 256);
    wsplit_kernel<<<(64*128 + 255)/256, 256>>>(r3, W3h, W3l, 64, 128, 128);

    // KNN + aggregation (split bf16 output)
    knn_kernel<<<dim3(NQ/256, B_), 256, NPTS*sizeof(float4)>>>(P, Q);
    agg_kernel<<<NTOT/8, 256>>>(Q);

    // Regressor on tensor cores via WMMA (split-bf16, fp32 accumulate)
    wm_gemm<256, KP1, true><<<dim3(NTOT/128, 4), 256>>>(AGGh, AGGl, W1h, W1l, rb1, H1h, H1l, nullptr);
    wm_gemm<128, 256, true><<<dim3(NTOT/128, 2), 256>>>(H1h, H1l, W2h, W2l, rb2, H2h, H2l, nullptr);
    wm_gemm<64, 128, false><<<dim3(NTOT/128, 1), 256>>>(H2h, H2l, W3h, W3l, rb3, nullptr, nullptr, H3);
    final_kernel<<<NTOT/256, 256>>>(r4, rb4, out);
}